// round 3
// baseline (speedup 1.0000x reference)
#include <cuda_runtime.h>

// Problem constants (fixed by setup_inputs)
#define NB     32      // batch
#define NH     12      // heads
#define P      784     // patches
#define PP     785     // patch_num + 1
#define TOPK   24      // VOTE_PERHEAD == select_num
#define HG     28      // 28x28 grid
#define VOTE_THREADS 256
#define SEL_THREADS  256

// Vote histogram scratch: integer counts, exact arithmetic throughout.
__device__ int g_count[NB * P];

// ---------------------------------------------------------------------------
// Kernel 0: zero the vote histogram (graph re-runs require explicit reset).
// ---------------------------------------------------------------------------
__global__ void zero_counts_kernel() {
    int i = blockIdx.x * blockDim.x + threadIdx.x;
    if (i < NB * P) g_count[i] = 0;
}

// ---------------------------------------------------------------------------
// Kernel 1: one block per (b, head). Load the 784 contiguous scores
// x[b,h,0,1:], compute each element's stable-descending rank by all-pairs
// comparison (strictly greater, or equal with lower index -> lax.top_k
// tie-break), and vote (+1 into the batch histogram) for elements with
// rank < 24. Inner loop: sc[j] is a broadcast LDS -> conflict-free.
// ---------------------------------------------------------------------------
__global__ __launch_bounds__(VOTE_THREADS)
void vote_kernel(const float* __restrict__ x) {
    const int bh = blockIdx.x;          // 0 .. NB*NH-1
    const int b  = bh / NH;
    const float* __restrict__ s = x + (size_t)bh * (PP * PP) + 1; // x[b,h,0,1:]

    __shared__ float sc[P];
    for (int i = threadIdx.x; i < P; i += VOTE_THREADS) sc[i] = s[i];
    __syncthreads();

    // Each thread owns up to 4 elements (784 = 3*256 + 16).
    int   idx[4];
    float v[4];
    int   cnt[4];
    int n = 0;
    for (int i = threadIdx.x; i < P; i += VOTE_THREADS) {
        idx[n] = i; v[n] = sc[i]; cnt[n] = 0; ++n;
    }

    for (int j = 0; j < P; ++j) {
        const float sj = sc[j];
        #pragma unroll
        for (int k = 0; k < 4; ++k)
            if (k < n)
                cnt[k] += (sj > v[k]) || (sj == v[k] && j < idx[k]);
    }

    #pragma unroll
    for (int k = 0; k < 4; ++k)
        if (k < n && cnt[k] < TOPK)
            atomicAdd(&g_count[b * P + idx[k]], 1);
}

// ---------------------------------------------------------------------------
// Kernel 2: one block per batch. 3x3 integer blur (SAME padding) of the
// 28x28 vote grid, then stable-descending rank of every element:
//   rank(i) = #{j : v[j] > v[i]} + #{j < i : v[j] == v[i]}
// Each rank in 0..P-1 occurs exactly once, so ranks < 24 scatter directly
// into the output slots, reproducing argsort(-count)[:24] + 1 exactly.
// Output dtype is FLOAT32 (the dataset records the reference output as
// float) -> write (float)(idx+1), exactly representable.
// ---------------------------------------------------------------------------
__global__ __launch_bounds__(SEL_THREADS)
void select_kernel(float* __restrict__ out) {
    const int b = blockIdx.x;

    __shared__ int cnt[P];
    __shared__ int blur[P];

    for (int i = threadIdx.x; i < P; i += SEL_THREADS)
        cnt[i] = g_count[b * P + i];
    __syncthreads();

    // 3x3 blur, weights {{1,2,1},{2,4,2},{1,2,1}} (symmetric -> conv == xcorr)
    for (int i = threadIdx.x; i < P; i += SEL_THREADS) {
        const int r = i / HG, c = i % HG;
        int acc = 0;
        #pragma unroll
        for (int dr = -1; dr <= 1; ++dr) {
            const int rr = r + dr;
            if (rr < 0 || rr >= HG) continue;
            #pragma unroll
            for (int dc = -1; dc <= 1; ++dc) {
                const int cc = c + dc;
                if (cc < 0 || cc >= HG) continue;
                const int w = ((dr == 0) ? 2 : 1) * ((dc == 0) ? 2 : 1);
                acc += w * cnt[rr * HG + cc];
            }
        }
        blur[i] = acc;
    }
    __syncthreads();

    int idx[4];
    int v[4];
    int rk[4];
    int n = 0;
    for (int i = threadIdx.x; i < P; i += SEL_THREADS) {
        idx[n] = i; v[n] = blur[i]; rk[n] = 0; ++n;
    }

    for (int j = 0; j < P; ++j) {
        const int bj = blur[j];
        #pragma unroll
        for (int k = 0; k < 4; ++k)
            if (k < n)
                rk[k] += (bj > v[k]) || (bj == v[k] && j < idx[k]);
    }

    #pragma unroll
    for (int k = 0; k < 4; ++k)
        if (k < n && rk[k] < TOPK)
            out[b * TOPK + rk[k]] = (float)(idx[k] + 1);
}

// ---------------------------------------------------------------------------
extern "C" void kernel_launch(void* const* d_in, const int* in_sizes, int n_in,
                              void* d_out, int out_size) {
    // Robust input selection: x is by far the largest input
    // (32*12*785*785 = 236,630,400 elements). Do not assume metadata order.
    int xi = 0;
    long long best = -1;
    for (int i = 0; i < n_in; ++i) {
        if ((long long)in_sizes[i] > best) { best = in_sizes[i]; xi = i; }
    }
    const float* x = (const float*)d_in[xi];
    float* out = (float*)d_out;              // (32,24) float32

    zero_counts_kernel<<<(NB * P + 255) / 256, 256>>>();
    vote_kernel<<<NB * NH, VOTE_THREADS>>>(x);
    select_kernel<<<NB, SEL_THREADS>>>(out);
}

// round 4
// speedup vs baseline: 5.5200x; 5.5200x over previous
#include <cuda_runtime.h>
#include <cstdint>

#define NB     32
#define NH     12
#define P      784
#define PP     785
#define TOPK   24
#define HG     28
#define VT     256       // vote threads
#define RT     256       // rank threads
#define RSPLIT 4         // rank blocks per batch
#define OWN_R  196       // P / RSPLIT

// Per-(b,h) selected indices: rank r in 0..23 -> index. Fully rewritten each
// run (each rank occurs exactly once), so no zeroing needed.
__device__ int g_sel[NB * NH * TOPK];

// Monotonic float32 -> uint32 order-preserving transform.
__device__ __forceinline__ uint32_t fkey(float f) {
    uint32_t b = __float_as_uint(f);
    return b ^ ((uint32_t)((int32_t)b >> 31) | 0x80000000u);
}

// ---------------------------------------------------------------------------
// Kernel 1: one block per (b,head). Build unique sortable keys
//   key[i] = (u32(value) << 10) | (1023 - i)
// (lower index -> larger key -> exact lax.top_k stable tie-break).
// Stable-descending rank of i = #{j : key[j] > key[i]}  (keys unique).
// Elements with rank < 24 write their index into g_sel[bh][rank].
// Inner loop: broadcast LDS.128 + branchless u64 compares.
// ---------------------------------------------------------------------------
__global__ __launch_bounds__(VT)
void vote_kernel(const float* __restrict__ x) {
    const int bh = blockIdx.x;                       // 0 .. NB*NH-1
    const float* __restrict__ s = x + (size_t)bh * (PP * PP) + 1;

    __shared__ __align__(16) unsigned long long key[P];
    for (int i = threadIdx.x; i < P; i += VT) {
        uint32_t u = fkey(s[i]);
        key[i] = ((unsigned long long)u << 10) | (unsigned)(1023 - i);
    }
    __syncthreads();

    // Each thread owns up to 4 elements (784 = 3*256 + 16).
    unsigned long long kv[4];
    int cnt[4];
    int idx[4];
    #pragma unroll
    for (int k = 0; k < 4; ++k) {
        int i = threadIdx.x + VT * k;
        idx[k] = i;
        kv[k]  = (i < P) ? key[i] : 0ULL;   // pad key 0 -> rank 784, never votes
        cnt[k] = 0;
    }

    const ulonglong2* __restrict__ key2 =
        reinterpret_cast<const ulonglong2*>(key);
    #pragma unroll 4
    for (int j2 = 0; j2 < P / 2; ++j2) {             // 392 x 2 keys
        const ulonglong2 q = key2[j2];
        #pragma unroll
        for (int k = 0; k < 4; ++k) {
            cnt[k] += (int)(q.x > kv[k]);
            cnt[k] += (int)(q.y > kv[k]);
        }
    }

    #pragma unroll
    for (int k = 0; k < 4; ++k)
        if (idx[k] < P && cnt[k] < TOPK)
            g_sel[bh * TOPK + cnt[k]] = idx[k];
}

// ---------------------------------------------------------------------------
// Kernel 2: 4 blocks per batch. Each block redundantly rebuilds the batch's
// vote histogram (288 shared-atomic increments) and the 3x3 integer blur
// (exact int arithmetic), packs blurred counts into unique sortable keys,
// then ranks its own 196 elements against all 784. Ranks < 24 scatter
// (float)(idx+1) into the output (stable order == argsort(-count)).
// ---------------------------------------------------------------------------
__global__ __launch_bounds__(RT)
void rank_kernel(float* __restrict__ out) {
    const int b    = blockIdx.x / RSPLIT;
    const int part = blockIdx.x % RSPLIT;

    __shared__ int cnt[P];
    __shared__ __align__(16) unsigned long long key[P];

    for (int i = threadIdx.x; i < P; i += RT) cnt[i] = 0;
    __syncthreads();

    for (int t = threadIdx.x; t < NH * TOPK; t += RT)
        atomicAdd(&cnt[g_sel[b * NH * TOPK + t]], 1);
    __syncthreads();

    // 3x3 blur, weights {{1,2,1},{2,4,2},{1,2,1}}, SAME padding (symmetric ->
    // conv == xcorr). Values stay small ints (max 16*288), exact.
    for (int i = threadIdx.x; i < P; i += RT) {
        const int r = i / HG, c = i % HG;
        int acc = 0;
        #pragma unroll
        for (int dr = -1; dr <= 1; ++dr) {
            const int rr = r + dr;
            if (rr < 0 || rr >= HG) continue;
            #pragma unroll
            for (int dc = -1; dc <= 1; ++dc) {
                const int cc = c + dc;
                if (cc < 0 || cc >= HG) continue;
                const int w = ((dr == 0) ? 2 : 1) * ((dc == 0) ? 2 : 1);
                acc += w * cnt[rr * HG + cc];
            }
        }
        key[i] = ((unsigned long long)acc << 10) | (unsigned)(1023 - i);
    }
    __syncthreads();

    const int i0 = part * OWN_R + threadIdx.x;       // owned element
    const bool active = (threadIdx.x < OWN_R);       // i0 < P guaranteed
    unsigned long long kv = active ? key[i0] : 0xFFFFFFFFFFFFFFFFULL;

    int rk = 0;
    const ulonglong2* __restrict__ key2 =
        reinterpret_cast<const ulonglong2*>(key);
    #pragma unroll 4
    for (int j2 = 0; j2 < P / 2; ++j2) {
        const ulonglong2 q = key2[j2];
        rk += (int)(q.x > kv);
        rk += (int)(q.y > kv);
    }

    if (active && rk < TOPK)
        out[b * TOPK + rk] = (float)(i0 + 1);
}

// ---------------------------------------------------------------------------
extern "C" void kernel_launch(void* const* d_in, const int* in_sizes, int n_in,
                              void* d_out, int out_size) {
    // x is by far the largest input (236,630,400 elements); don't assume order.
    int xi = 0;
    long long best = -1;
    for (int i = 0; i < n_in; ++i)
        if ((long long)in_sizes[i] > best) { best = in_sizes[i]; xi = i; }

    const float* x = (const float*)d_in[xi];
    float* out = (float*)d_out;                      // (32,24) float32

    vote_kernel<<<NB * NH, VT>>>(x);
    rank_kernel<<<NB * RSPLIT, RT>>>(out);
}

// round 5
// speedup vs baseline: 17.3445x; 3.1421x over previous
#include <cuda_runtime.h>
#include <cstdint>

#define NB     32
#define NH     12
#define P      784
#define PP     785
#define TOPK   24
#define HG     28
#define VT     256       // threads per block (both kernels)

// Per-(b,h) selected indices: rank r in 0..23 -> index. Every rank 0..23 is
// written exactly once per run (candidate set always >= 24), no zeroing.
__device__ int g_sel[NB * NH * TOPK];

// Monotonic float32 -> uint32 order-preserving transform.
__device__ __forceinline__ uint32_t fkey(float f) {
    uint32_t b = __float_as_uint(f);
    return b ^ ((uint32_t)((int32_t)b >> 31) | 0x80000000u);
}

// Suffix threshold over a 1024-bin shared histogram, coarse-grained to 256
// buckets of 4 bins. Returns (in *outB) the largest coarse bucket B with
// #keys in buckets >= B at least TOPK. Caller syncs. scan[] is 256 ints.
__device__ __forceinline__ void coarse_suffix_threshold(
        const int* __restrict__ hist, int* __restrict__ scan, int* outB) {
    const int t = threadIdx.x;
    if (t < 256)
        scan[t] = hist[4 * t] + hist[4 * t + 1] + hist[4 * t + 2] + hist[4 * t + 3];
    __syncthreads();
    #pragma unroll
    for (int off = 1; off < 256; off <<= 1) {
        int v = 0;
        if (t < 256 && t + off < 256) v = scan[t + off];
        __syncthreads();
        if (t < 256) scan[t] += v;
        __syncthreads();
    }
    // scan[t] = #keys in coarse buckets >= t (non-increasing, scan[0] = P).
    if (t < 256) {
        int nxt = (t == 255) ? 0 : scan[t + 1];
        if (scan[t] >= TOPK && nxt < TOPK) *outB = t;
    }
}

// ---------------------------------------------------------------------------
// Kernel 1: one block per (b,head). Radix-pruned exact top-24:
//  - fkeys of the 784 scores, 10-bit-top histogram
//  - coarse suffix threshold B; candidates = keys in coarse buckets >= B
//    (provably a superset of the top-24; all non-candidates strictly smaller)
//  - exact stable rank among candidates with unique u64 keys
//      key = (fkey << 10) | (1023 - idx)   (lower idx wins ties, lax.top_k)
// ---------------------------------------------------------------------------
__global__ __launch_bounds__(VT)
void vote_kernel(const float* __restrict__ x) {
    const int bh = blockIdx.x;
    const float* __restrict__ s = x + (size_t)bh * (PP * PP) + 1;

    __shared__ uint32_t fk[P];
    __shared__ int hist[1024];
    __shared__ int scan[256];
    __shared__ unsigned long long cand[P];
    __shared__ int sB, snc;

    for (int i = threadIdx.x; i < 1024; i += VT) hist[i] = 0;
    if (threadIdx.x == 0) snc = 0;
    __syncthreads();

    for (int i = threadIdx.x; i < P; i += VT) {
        uint32_t u = fkey(s[i]);
        fk[i] = u;
        atomicAdd(&hist[u >> 22], 1);
    }
    __syncthreads();

    coarse_suffix_threshold(hist, scan, &sB);
    __syncthreads();
    const uint32_t B = (uint32_t)sB;

    for (int i = threadIdx.x; i < P; i += VT) {
        uint32_t u = fk[i];
        if ((u >> 24) >= B) {
            int slot = atomicAdd(&snc, 1);
            cand[slot] = ((unsigned long long)u << 10) | (unsigned)(1023 - i);
        }
    }
    __syncthreads();

    const int nc = snc;   // >= TOPK by construction
    for (int t = threadIdx.x; t < nc; t += VT) {
        const unsigned long long kt = cand[t];
        int r = 0;
        for (int u = 0; u < nc; ++u)
            r += (int)(cand[u] > kt);
        if (r < TOPK)
            g_sel[bh * TOPK + r] = 1023 - (int)(kt & 1023u);
    }
}

// ---------------------------------------------------------------------------
// Kernel 2: one block per batch. Vote histogram from g_sel, exact-int 3x3
// blur ({{1,2,1},{2,4,2},{1,2,1}}, SAME), then the same radix-pruned exact
// stable-descending rank over blurred counts (bucket = min(blur,1023):
// capped values share the top bucket; below-threshold blurs are strictly
// smaller, so pruning is exact). Ranks < 24 scatter (float)(idx+1).
// ---------------------------------------------------------------------------
__global__ __launch_bounds__(VT)
void rank_kernel(float* __restrict__ out) {
    const int b = blockIdx.x;

    __shared__ int cnt[P];
    __shared__ int blurv[P];
    __shared__ int hist[1024];
    __shared__ int scan[256];
    __shared__ unsigned long long cand[P];
    __shared__ int sB, snc;

    for (int i = threadIdx.x; i < P; i += VT) cnt[i] = 0;
    for (int i = threadIdx.x; i < 1024; i += VT) hist[i] = 0;
    if (threadIdx.x == 0) snc = 0;
    __syncthreads();

    for (int t = threadIdx.x; t < NH * TOPK; t += VT)
        atomicAdd(&cnt[g_sel[b * NH * TOPK + t]], 1);
    __syncthreads();

    for (int i = threadIdx.x; i < P; i += VT) {
        const int r = i / HG, c = i % HG;
        int acc = 0;
        #pragma unroll
        for (int dr = -1; dr <= 1; ++dr) {
            const int rr = r + dr;
            if (rr < 0 || rr >= HG) continue;
            #pragma unroll
            for (int dc = -1; dc <= 1; ++dc) {
                const int cc = c + dc;
                if (cc < 0 || cc >= HG) continue;
                const int w = ((dr == 0) ? 2 : 1) * ((dc == 0) ? 2 : 1);
                acc += w * cnt[rr * HG + cc];
            }
        }
        blurv[i] = acc;
        int bin = acc < 1023 ? acc : 1023;
        atomicAdd(&hist[bin], 1);
    }
    __syncthreads();

    coarse_suffix_threshold(hist, scan, &sB);
    __syncthreads();
    const int B = sB;

    for (int i = threadIdx.x; i < P; i += VT) {
        int v = blurv[i];
        int bin = v < 1023 ? v : 1023;
        if ((bin >> 2) >= B) {
            int slot = atomicAdd(&snc, 1);
            cand[slot] = ((unsigned long long)v << 10) | (unsigned)(1023 - i);
        }
    }
    __syncthreads();

    const int nc = snc;   // >= TOPK
    for (int t = threadIdx.x; t < nc; t += VT) {
        const unsigned long long kt = cand[t];
        int r = 0;
        for (int u = 0; u < nc; ++u)
            r += (int)(cand[u] > kt);
        if (r < TOPK)
            out[b * TOPK + r] = (float)(1024 - (int)(kt & 1023u));  // idx+1
    }
}

// ---------------------------------------------------------------------------
extern "C" void kernel_launch(void* const* d_in, const int* in_sizes, int n_in,
                              void* d_out, int out_size) {
    // x is by far the largest input (236,630,400 elements); don't assume order.
    int xi = 0;
    long long best = -1;
    for (int i = 0; i < n_in; ++i)
        if ((long long)in_sizes[i] > best) { best = in_sizes[i]; xi = i; }

    const float* x = (const float*)d_in[xi];
    float* out = (float*)d_out;                      // (32,24) float32

    vote_kernel<<<NB * NH, VT>>>(x);
    rank_kernel<<<NB, VT>>>(out);
}

// round 6
// speedup vs baseline: 25.9300x; 1.4950x over previous
#include <cuda_runtime.h>
#include <cstdint>

#define NB     32
#define NH     12
#define P      784
#define PP     785
#define TOPK   24
#define HG     28
#define VT     256

// Per-(b,h) selected indices (rank r -> index). Each slot rewritten every run.
__device__ int g_sel[NB * NH * TOPK];
// Per-batch completion counters; always returned to 0 by the last block.
__device__ int g_done[NB];

// Monotonic float32 -> uint32 order-preserving transform.
__device__ __forceinline__ uint32_t fkey(float f) {
    uint32_t b = __float_as_uint(f);
    return b ^ ((uint32_t)((int32_t)b >> 31) | 0x80000000u);
}

// Warp-0 suffix-threshold over hist[1024]: finds largest bin B with
// (#keys in bins >= B) >= TOPK, writes it to *sB. Call from ALL lanes of
// warp 0; caller syncs afterwards. Exactly one lane/bin satisfies the
// boundary condition (suffix is non-increasing, suffix(0) = P >= TOPK).
__device__ __forceinline__ void warp_suffix_threshold(
        const int* __restrict__ hist, int* __restrict__ sB) {
    const int l = threadIdx.x;   // 0..31
    int tot = 0;
    #pragma unroll 8
    for (int k = 0; k < 32; ++k) tot += hist[32 * l + k];
    int s = tot;
    #pragma unroll
    for (int off = 1; off < 32; off <<= 1) {
        int o = __shfl_down_sync(0xffffffffu, s, off);
        s += (l + off < 32) ? o : 0;          // inclusive suffix of lane totals
    }
    const int after = s - tot;                // suffix strictly after this lane
    if (s >= TOPK && after < TOPK) {          // boundary bin lives in this lane
        int run = after, nxt = after, B = 0;
        #pragma unroll 8
        for (int k = 31; k >= 0; --k) {
            run += hist[32 * l + k];
            if (run >= TOPK && nxt < TOPK) B = 32 * l + k;
            nxt = run;
        }
        *sB = B;
    }
}

// ---------------------------------------------------------------------------
// Fused kernel: one block per (b, head).
// Phase V: radix-pruned exact stable top-24 of the 784 scores x[b,h,0,1:]
//   (1024-bin histogram of fkey>>22, warp suffix threshold, all-pairs rank
//    among the ~32 candidates with unique keys (fkey<<10)|(1023-idx)).
// The last block to finish in its batch (release/acquire via g_done) runs
// Phase R: vote histogram, exact-int 3x3 blur (SAME), same radix-pruned
//   stable rank of blurred counts, scatter (float)(idx+1) into out.
// ---------------------------------------------------------------------------
__global__ __launch_bounds__(VT)
void fused_kernel(const float* __restrict__ x, float* __restrict__ out) {
    const int bh = blockIdx.x;
    const int b  = bh / NH;
    const float* __restrict__ s = x + (size_t)bh * (PP * PP) + 1;

    __shared__ uint32_t fk[P];                 // phase V: fkeys; phase R: counts
    __shared__ int      blurv[P];
    __shared__ int      hist[1024];
    __shared__ unsigned long long cand[P];
    __shared__ int sB, snc, slast;

    const int t = threadIdx.x;

    // ---------------- Phase V ----------------
    for (int i = t; i < 1024; i += VT) hist[i] = 0;
    if (t == 0) snc = 0;
    __syncthreads();

    for (int i = t; i < P; i += VT) {
        uint32_t u = fkey(s[i]);
        fk[i] = u;
        atomicAdd(&hist[u >> 22], 1);
    }
    __syncthreads();

    if (t < 32) warp_suffix_threshold(hist, &sB);
    __syncthreads();
    const uint32_t B = (uint32_t)sB;

    for (int i = t; i < P; i += VT) {
        uint32_t u = fk[i];
        if ((u >> 22) >= B) {
            int slot = atomicAdd(&snc, 1);
            cand[slot] = ((unsigned long long)u << 10) | (unsigned)(1023 - i);
        }
    }
    __syncthreads();

    const int nc = snc;                        // >= TOPK by construction
    for (int c = t; c < nc; c += VT) {
        const unsigned long long kt = cand[c];
        int r = 0;
        for (int u = 0; u < nc; ++u) r += (int)(cand[u] > kt);
        if (r < TOPK) g_sel[bh * TOPK + r] = 1023 - (int)(kt & 1023u);
    }
    __syncthreads();

    // -------- last-block-per-batch election (release/acquire) --------
    if (t == 0) {
        __threadfence();                       // publish g_sel writes
        int prev = atomicAdd(&g_done[b], 1);
        slast = (prev == NH - 1);
        if (slast) g_done[b] = 0;              // reset for next graph replay
    }
    __syncthreads();
    if (!slast) return;
    __threadfence();                           // acquire all heads' g_sel

    // ---------------- Phase R ----------------
    for (int i = t; i < P; i += VT) fk[i] = 0;          // fk := vote counts
    for (int i = t; i < 1024; i += VT) hist[i] = 0;
    if (t == 0) snc = 0;
    __syncthreads();

    for (int v = t; v < NH * TOPK; v += VT)
        atomicAdd(&fk[g_sel[b * NH * TOPK + v]], 1u);
    __syncthreads();

    // 3x3 blur, weights {{1,2,1},{2,4,2},{1,2,1}}, SAME padding (symmetric
    // -> conv == xcorr); exact small-int arithmetic.
    for (int i = t; i < P; i += VT) {
        const int r = i / HG, c = i % HG;
        int acc = 0;
        #pragma unroll
        for (int dr = -1; dr <= 1; ++dr) {
            const int rr = r + dr;
            if (rr < 0 || rr >= HG) continue;
            #pragma unroll
            for (int dc = -1; dc <= 1; ++dc) {
                const int cc = c + dc;
                if (cc < 0 || cc >= HG) continue;
                const int w = ((dr == 0) ? 2 : 1) * ((dc == 0) ? 2 : 1);
                acc += w * (int)fk[rr * HG + cc];
            }
        }
        blurv[i] = acc;
        int bin = acc < 1023 ? acc : 1023;     // cap keeps bucket order exact
        atomicAdd(&hist[bin], 1);
    }
    __syncthreads();

    if (t < 32) warp_suffix_threshold(hist, &sB);
    __syncthreads();
    const int B2 = sB;

    for (int i = t; i < P; i += VT) {
        int v = blurv[i];
        int bin = v < 1023 ? v : 1023;
        if (bin >= B2) {
            int slot = atomicAdd(&snc, 1);
            cand[slot] = ((unsigned long long)v << 10) | (unsigned)(1023 - i);
        }
    }
    __syncthreads();

    const int nc2 = snc;                       // >= TOPK
    for (int c = t; c < nc2; c += VT) {
        const unsigned long long kt = cand[c];
        int r = 0;
        for (int u = 0; u < nc2; ++u) r += (int)(cand[u] > kt);
        if (r < TOPK)
            out[b * TOPK + r] = (float)(1024 - (int)(kt & 1023u));  // idx+1
    }
}

// ---------------------------------------------------------------------------
extern "C" void kernel_launch(void* const* d_in, const int* in_sizes, int n_in,
                              void* d_out, int out_size) {
    // x is by far the largest input (236,630,400 elements); don't assume order.
    int xi = 0;
    long long best = -1;
    for (int i = 0; i < n_in; ++i)
        if ((long long)in_sizes[i] > best) { best = in_sizes[i]; xi = i; }

    const float* x = (const float*)d_in[xi];
    float* out = (float*)d_out;                      // (32,24) float32

    fused_kernel<<<NB * NH, VT>>>(x, out);
}